// round 12
// baseline (speedup 1.0000x reference)
#include <cuda_runtime.h>
#include <cstdio>

#define NN 50000
#define NE 800000
#define FI 128
#define FH 128
#define FC 64

// ---------------- scratch (device globals; no allocation allowed) ----------------
__device__ int   g_cntI[NN];                       // in-degree (int)
__device__ int   g_off[NN + 1];                    // CSR offsets (by dst)
__device__ int   g_cur[NN];                        // fill cursors
__device__ int   g_csrc[NE];                       // CSR src lists
__device__ float g_cnt[NN];                        // in-degree (float)
__device__ float g_dinv[NN];                       // rsqrt(in-degree + 1) for GCN
__device__ __align__(16) float g_h1[NN * FH];      // SAGE1 output (post-relu)
__device__ __align__(16) float g_xw[NN * FC];      // h2 @ Wg

// ---------------- CSR build (edge_index is INT32 [2, E]) ----------------
__global__ void k_zero_cnt() {
    int i = blockIdx.x * blockDim.x + threadIdx.x;
    if (i < NN) g_cntI[i] = 0;
}

__global__ void k_count(const int* __restrict__ ei) {
    int e = blockIdx.x * blockDim.x + threadIdx.x;
    if (e < NE) atomicAdd(g_cntI + ei[NE + e], 1);
}

// single-block exclusive scan over NN counts -> offsets + cursors + cnt/dinv
__global__ void k_scan() {
    __shared__ int part[1024];
    const int CH = (NN + 1023) / 1024;   // 49
    int t = threadIdx.x;
    int base = t * CH;
    int sum = 0;
    for (int i = 0; i < CH; i++) {
        int idx = base + i;
        if (idx < NN) sum += g_cntI[idx];
    }
    part[t] = sum;
    __syncthreads();
    for (int off = 1; off < 1024; off <<= 1) {
        int v = (t >= off) ? part[t - off] : 0;
        __syncthreads();
        part[t] += v;
        __syncthreads();
    }
    int run = part[t] - sum;
    for (int i = 0; i < CH; i++) {
        int idx = base + i;
        if (idx < NN) {
            int c = g_cntI[idx];
            g_off[idx] = run;
            g_cur[idx] = run;
            run += c;
            g_cnt[idx] = (float)c;
            g_dinv[idx] = rsqrtf((float)c + 1.0f);
        }
    }
    if (t == 1023) g_off[NN] = NE;
}

__global__ void k_fill(const int* __restrict__ ei) {
    int e = blockIdx.x * blockDim.x + threadIdx.x;
    if (e >= NE) return;
    int src = ei[e];
    int dst = ei[NE + e];
    int pos = atomicAdd(g_cur + dst, 1);
    g_csrc[pos] = src;
}

// ---------------- fused SAGE1: gather(x) + mean + GEMM + relu, persistent ----------------
// 32 nodes/tile; 256 threads; warp owns 4 nodes; lane owns 4 output cols (float4).
// smem: W1l 64KB + W1r 64KB + sM 16KB + sX 16KB = 160KB dynamic.
#define S1_NODES 32
__global__ void __launch_bounds__(256) k_sage1_fused(const float* __restrict__ x,
                                                     const float* __restrict__ W1l,
                                                     const float* __restrict__ b1l,
                                                     const float* __restrict__ W1r) {
    extern __shared__ float sm[];
    float* sWl = sm;                       // [128][128]
    float* sWr = sWl + FI * FH;            // [128][128]
    float* sM  = sWr + FI * FH;            // [32][128]
    float* sX  = sM + S1_NODES * FI;       // [32][128]
    int t = threadIdx.x;
    int warp = t >> 5, lane = t & 31;
    int nl0 = warp * 4;

    for (int i = t; i < FI * FH / 4; i += 256) {
        ((float4*)sWl)[i] = ((const float4*)W1l)[i];
        ((float4*)sWr)[i] = ((const float4*)W1r)[i];
    }
    float4 bb = ((const float4*)b1l)[lane];

    const int ntiles = (NN + S1_NODES - 1) / S1_NODES;   // 1563
    for (int tile = blockIdx.x; tile < ntiles; tile += gridDim.x) {
        int nbase = tile * S1_NODES;
        __syncthreads();   // protect sM/sX from previous tile's readers

        // gather phase: warp handles its 4 nodes sequentially, lane owns a float4
        #pragma unroll
        for (int r = 0; r < 4; r++) {
            int nl = nl0 + r;
            int gn = nbase + nl;
            float4 acc = make_float4(0.f, 0.f, 0.f, 0.f);
            float4 xv  = make_float4(0.f, 0.f, 0.f, 0.f);
            if (gn < NN) {
                int beg = g_off[gn], end = g_off[gn + 1];
                int j = beg;
                for (; j + 3 < end; j += 4) {
                    int s0 = g_csrc[j], s1 = g_csrc[j + 1], s2 = g_csrc[j + 2], s3 = g_csrc[j + 3];
                    float4 A = ((const float4*)(x + (size_t)s0 * FI))[lane];
                    float4 B = ((const float4*)(x + (size_t)s1 * FI))[lane];
                    float4 C = ((const float4*)(x + (size_t)s2 * FI))[lane];
                    float4 D = ((const float4*)(x + (size_t)s3 * FI))[lane];
                    acc.x += (A.x + B.x) + (C.x + D.x);
                    acc.y += (A.y + B.y) + (C.y + D.y);
                    acc.z += (A.z + B.z) + (C.z + D.z);
                    acc.w += (A.w + B.w) + (C.w + D.w);
                }
                for (; j < end; j++) {
                    int s0 = g_csrc[j];
                    float4 A = ((const float4*)(x + (size_t)s0 * FI))[lane];
                    acc.x += A.x; acc.y += A.y; acc.z += A.z; acc.w += A.w;
                }
                float sc = 1.0f / fmaxf(g_cnt[gn], 1.0f);
                acc.x *= sc; acc.y *= sc; acc.z *= sc; acc.w *= sc;
                xv = ((const float4*)(x + (size_t)gn * FI))[lane];
            }
            ((float4*)(sM + nl * FI))[lane] = acc;
            ((float4*)(sX + nl * FI))[lane] = xv;
        }
        __syncthreads();

        // GEMM phase: 4 nodes x 4 cols per lane
        float4 a0 = bb, a1 = bb, a2 = bb, a3 = bb;
        #pragma unroll 4
        for (int k = 0; k < FI; k++) {
            float4 wl = ((const float4*)sWl)[k * 32 + lane];
            float4 wr = ((const float4*)sWr)[k * 32 + lane];
            float m0 = sM[(nl0 + 0) * FI + k], x0 = sX[(nl0 + 0) * FI + k];
            float m1 = sM[(nl0 + 1) * FI + k], x1 = sX[(nl0 + 1) * FI + k];
            float m2 = sM[(nl0 + 2) * FI + k], x2 = sX[(nl0 + 2) * FI + k];
            float m3 = sM[(nl0 + 3) * FI + k], x3 = sX[(nl0 + 3) * FI + k];
            a0.x += m0 * wl.x + x0 * wr.x;  a0.y += m0 * wl.y + x0 * wr.y;
            a0.z += m0 * wl.z + x0 * wr.z;  a0.w += m0 * wl.w + x0 * wr.w;
            a1.x += m1 * wl.x + x1 * wr.x;  a1.y += m1 * wl.y + x1 * wr.y;
            a1.z += m1 * wl.z + x1 * wr.z;  a1.w += m1 * wl.w + x1 * wr.w;
            a2.x += m2 * wl.x + x2 * wr.x;  a2.y += m2 * wl.y + x2 * wr.y;
            a2.z += m2 * wl.z + x2 * wr.z;  a2.w += m2 * wl.w + x2 * wr.w;
            a3.x += m3 * wl.x + x3 * wr.x;  a3.y += m3 * wl.y + x3 * wr.y;
            a3.z += m3 * wl.z + x3 * wr.z;  a3.w += m3 * wl.w + x3 * wr.w;
        }
        #pragma unroll
        for (int r = 0; r < 4; r++) {
            int gn = nbase + nl0 + r;
            if (gn < NN) {
                float4 a = (r == 0) ? a0 : (r == 1) ? a1 : (r == 2) ? a2 : a3;
                float4 o = make_float4(fmaxf(a.x, 0.f), fmaxf(a.y, 0.f),
                                       fmaxf(a.z, 0.f), fmaxf(a.w, 0.f));
                ((float4*)(g_h1 + (size_t)gn * FH))[lane] = o;
            }
        }
    }
}

// ---------------- fused tail: gather(h1) + SAGE2 GEMM + softmax + GCN GEMM + epilogue ----------------
// 32 nodes/tile; 256 threads; warp owns 4 nodes; lane owns cols (lane, lane+32).
// smem: W2l 32KB + W2r 32KB + Wg 16KB + sM 16KB + sH 16KB + sH2 8KB = 120KB dynamic.
__global__ void __launch_bounds__(256) k_tail_fused(const float* __restrict__ W2l,
                                                    const float* __restrict__ b2l,
                                                    const float* __restrict__ W2r,
                                                    const float* __restrict__ Wg,
                                                    const float* __restrict__ bg,
                                                    float* __restrict__ out) {
    extern __shared__ float sm[];
    float* sWl = sm;                       // [128][64]
    float* sWr = sWl + FH * FC;            // [128][64]
    float* sWg = sWr + FH * FC;            // [64][64]
    float* sM  = sWg + FC * FC;            // [32][128]
    float* sH  = sM + S1_NODES * FH;       // [32][128]
    float* sH2 = sH + S1_NODES * FH;       // [32][64]
    int t = threadIdx.x;
    int warp = t >> 5, lane = t & 31;
    int nl0 = warp * 4;
    int cA = lane, cB = lane + 32;

    for (int i = t; i < FH * FC / 4; i += 256) {
        ((float4*)sWl)[i] = ((const float4*)W2l)[i];
        ((float4*)sWr)[i] = ((const float4*)W2r)[i];
    }
    for (int i = t; i < FC * FC / 4; i += 256) ((float4*)sWg)[i] = ((const float4*)Wg)[i];
    float bA = b2l[cA], bB = b2l[cB];
    float bgA = bg[cA], bgB = bg[cB];

    const int ntiles = (NN + S1_NODES - 1) / S1_NODES;
    for (int tile = blockIdx.x; tile < ntiles; tile += gridDim.x) {
        int nbase = tile * S1_NODES;
        __syncthreads();

        // gather h1 into sM (mean-scaled) + own h1 row into sH
        #pragma unroll
        for (int r = 0; r < 4; r++) {
            int nl = nl0 + r;
            int gn = nbase + nl;
            float4 acc = make_float4(0.f, 0.f, 0.f, 0.f);
            float4 hv  = make_float4(0.f, 0.f, 0.f, 0.f);
            if (gn < NN) {
                int beg = g_off[gn], end = g_off[gn + 1];
                int j = beg;
                for (; j + 3 < end; j += 4) {
                    int s0 = g_csrc[j], s1 = g_csrc[j + 1], s2 = g_csrc[j + 2], s3 = g_csrc[j + 3];
                    float4 A = ((const float4*)(g_h1 + (size_t)s0 * FH))[lane];
                    float4 B = ((const float4*)(g_h1 + (size_t)s1 * FH))[lane];
                    float4 C = ((const float4*)(g_h1 + (size_t)s2 * FH))[lane];
                    float4 D = ((const float4*)(g_h1 + (size_t)s3 * FH))[lane];
                    acc.x += (A.x + B.x) + (C.x + D.x);
                    acc.y += (A.y + B.y) + (C.y + D.y);
                    acc.z += (A.z + B.z) + (C.z + D.z);
                    acc.w += (A.w + B.w) + (C.w + D.w);
                }
                for (; j < end; j++) {
                    int s0 = g_csrc[j];
                    float4 A = ((const float4*)(g_h1 + (size_t)s0 * FH))[lane];
                    acc.x += A.x; acc.y += A.y; acc.z += A.z; acc.w += A.w;
                }
                float sc = 1.0f / fmaxf(g_cnt[gn], 1.0f);
                acc.x *= sc; acc.y *= sc; acc.z *= sc; acc.w *= sc;
                hv = ((const float4*)(g_h1 + (size_t)gn * FH))[lane];
            }
            ((float4*)(sM + nl * FH))[lane] = acc;
            ((float4*)(sH + nl * FH))[lane] = hv;
        }
        __syncthreads();

        // SAGE2 GEMM: 4 nodes x 2 cols per lane
        float a00 = bA, a01 = bB, a10 = bA, a11 = bB;
        float a20 = bA, a21 = bB, a30 = bA, a31 = bB;
        #pragma unroll 4
        for (int k = 0; k < FH; k++) {
            float wlA = sWl[k * FC + cA], wlB = sWl[k * FC + cB];
            float wrA = sWr[k * FC + cA], wrB = sWr[k * FC + cB];
            float m0 = sM[(nl0 + 0) * FH + k], h0 = sH[(nl0 + 0) * FH + k];
            float m1 = sM[(nl0 + 1) * FH + k], h1 = sH[(nl0 + 1) * FH + k];
            float m2 = sM[(nl0 + 2) * FH + k], h2 = sH[(nl0 + 2) * FH + k];
            float m3 = sM[(nl0 + 3) * FH + k], h3 = sH[(nl0 + 3) * FH + k];
            a00 += m0 * wlA + h0 * wrA;  a01 += m0 * wlB + h0 * wrB;
            a10 += m1 * wlA + h1 * wrA;  a11 += m1 * wlB + h1 * wrB;
            a20 += m2 * wlA + h2 * wrA;  a21 += m2 * wlB + h2 * wrB;
            a30 += m3 * wlA + h3 * wrA;  a31 += m3 * wlB + h3 * wrB;
        }

        // softmax per node (row of 64 lives across the warp: cols lane, lane+32)
        float e00, e01, e10, e11, e20, e21, e30, e31;
        {
            float v0[4] = {a00, a10, a20, a30};
            float v1[4] = {a01, a11, a21, a31};
            float eo0[4], eo1[4];
            #pragma unroll
            for (int r = 0; r < 4; r++) {
                float mx = fmaxf(v0[r], v1[r]);
                #pragma unroll
                for (int o = 16; o > 0; o >>= 1) mx = fmaxf(mx, __shfl_xor_sync(0xFFFFFFFFu, mx, o));
                float e0 = __expf(v0[r] - mx), e1 = __expf(v1[r] - mx);
                float s = e0 + e1;
                #pragma unroll
                for (int o = 16; o > 0; o >>= 1) s += __shfl_xor_sync(0xFFFFFFFFu, s, o);
                float inv = 1.0f / s;
                eo0[r] = e0 * inv; eo1[r] = e1 * inv;
            }
            e00 = eo0[0]; e10 = eo0[1]; e20 = eo0[2]; e30 = eo0[3];
            e01 = eo1[0]; e11 = eo1[1]; e21 = eo1[2]; e31 = eo1[3];
        }
        // stage h2 rows in smem (own warp's rows only -> syncwarp suffices)
        sH2[(nl0 + 0) * FC + cA] = e00;  sH2[(nl0 + 0) * FC + cB] = e01;
        sH2[(nl0 + 1) * FC + cA] = e10;  sH2[(nl0 + 1) * FC + cB] = e11;
        sH2[(nl0 + 2) * FC + cA] = e20;  sH2[(nl0 + 2) * FC + cB] = e21;
        sH2[(nl0 + 3) * FC + cA] = e30;  sH2[(nl0 + 3) * FC + cB] = e31;
        __syncwarp();

        // GCN GEMM: xw = h2 @ Wg
        float g00 = 0.f, g01 = 0.f, g10 = 0.f, g11 = 0.f;
        float g20 = 0.f, g21 = 0.f, g30 = 0.f, g31 = 0.f;
        #pragma unroll 4
        for (int k = 0; k < FC; k++) {
            float wA = sWg[k * FC + cA], wB = sWg[k * FC + cB];
            float f0 = sH2[(nl0 + 0) * FC + k];
            float f1 = sH2[(nl0 + 1) * FC + k];
            float f2 = sH2[(nl0 + 2) * FC + k];
            float f3 = sH2[(nl0 + 3) * FC + k];
            g00 += f0 * wA; g01 += f0 * wB;
            g10 += f1 * wA; g11 += f1 * wB;
            g20 += f2 * wA; g21 += f2 * wB;
            g30 += f3 * wA; g31 += f3 * wB;
        }

        // epilogue: g_xw + self-loop part of out
        float gx0[4] = {g00, g10, g20, g30};
        float gx1[4] = {g01, g11, g21, g31};
        #pragma unroll
        for (int r = 0; r < 4; r++) {
            int gn = nbase + nl0 + r;
            if (gn < NN) {
                float d = g_dinv[gn];
                float d2 = d * d;
                size_t base = (size_t)gn * FC;
                g_xw[base + cA] = gx0[r];
                g_xw[base + cB] = gx1[r];
                out[base + cA] = bgA + d2 * gx0[r];
                out[base + cB] = bgB + d2 * gx1[r];
            }
        }
    }
}

// ---------------- GCN edge gather: out[n] += dinv[n] * sum dinv[src]*xw[src] ----------------
__global__ void k_ggather(float* __restrict__ out) {
    int gt = blockIdx.x * blockDim.x + threadIdx.x;
    int node = gt >> 5;
    int lane = gt & 31;
    if (node >= NN) return;
    int beg = g_off[node], end = g_off[node + 1];
    float accA = 0.f, accB = 0.f;
    int j = beg;
    for (; j + 1 < end; j += 2) {
        int s0 = g_csrc[j], s1 = g_csrc[j + 1];
        float d0 = g_dinv[s0], d1 = g_dinv[s1];
        const float* r0 = g_xw + (size_t)s0 * FC;
        const float* r1 = g_xw + (size_t)s1 * FC;
        accA += d0 * r0[lane] + d1 * r1[lane];
        accB += d0 * r0[lane + 32] + d1 * r1[lane + 32];
    }
    if (j < end) {
        int s = g_csrc[j];
        float ds = g_dinv[s];
        const float* r = g_xw + (size_t)s * FC;
        accA += ds * r[lane];
        accB += ds * r[lane + 32];
    }
    float dn = g_dinv[node];
    float* row = out + (size_t)node * FC;
    row[lane] += dn * accA;
    row[lane + 32] += dn * accB;
}

// ---------------- launch ----------------
static void hx_check(const char* name, bool docheck, bool* bad) {
    if (!docheck || *bad) return;
    cudaError_t e = cudaStreamSynchronize(0);
    if (e != cudaSuccess) {
        fprintf(stderr, "HXDBG fault after %s: %s\n", name, cudaGetErrorString(e));
        fflush(stderr);
        *bad = true;
    }
}

extern "C" void kernel_launch(void* const* d_in, const int* in_sizes, int n_in,
                              void* d_out, int out_size) {
    const float* x   = (const float*)d_in[0];
    const int* ei    = (const int*)d_in[1];   // INT32 [2, E]
    const float* W1l = (const float*)d_in[2];
    const float* b1l = (const float*)d_in[3];
    const float* W1r = (const float*)d_in[4];
    const float* W2l = (const float*)d_in[5];
    const float* b2l = (const float*)d_in[6];
    const float* W2r = (const float*)d_in[7];
    const float* Wg  = (const float*)d_in[8];
    const float* bg  = (const float*)d_in[9];
    float* out = (float*)d_out;

    const int SMEM1 = (FI * FH * 2 + S1_NODES * FI * 2) * 4;                 // 163840
    const int SMEM2 = (FH * FC * 2 + FC * FC + S1_NODES * FH * 2 + S1_NODES * FC) * 4;  // 122880
    cudaFuncSetAttribute(k_sage1_fused, cudaFuncAttributeMaxDynamicSharedMemorySize, SMEM1);
    cudaFuncSetAttribute(k_tail_fused, cudaFuncAttributeMaxDynamicSharedMemorySize, SMEM2);

    cudaStreamCaptureStatus st = cudaStreamCaptureStatusNone;
    cudaStreamIsCapturing(0, &st);
    bool docheck = (st == cudaStreamCaptureStatusNone);
    bool bad = false;

    // CSR build (by dst)
    k_zero_cnt<<<(NN + 255) / 256, 256>>>();
    hx_check("k_zero_cnt", docheck, &bad);
    k_count<<<(NE + 255) / 256, 256>>>(ei);
    hx_check("k_count", docheck, &bad);
    k_scan<<<1, 1024>>>();
    hx_check("k_scan", docheck, &bad);
    k_fill<<<(NE + 255) / 256, 256>>>(ei);
    hx_check("k_fill", docheck, &bad);

    // fused layers
    k_sage1_fused<<<148, 256, SMEM1>>>(x, W1l, b1l, W1r);
    hx_check("k_sage1_fused", docheck, &bad);
    k_tail_fused<<<148, 256, SMEM2>>>(W2l, b2l, W2r, Wg, bg, out);
    hx_check("k_tail_fused", docheck, &bad);
    k_ggather<<<(NN * 32 + 255) / 256, 256>>>(out);
    hx_check("k_ggather", docheck, &bad);
}

// round 14
// speedup vs baseline: 1.1621x; 1.1621x over previous
#include <cuda_runtime.h>
#include <cstdio>

#define NN 50000
#define NE 800000
#define FI 128
#define FH 128
#define FC 64

// ---------------- scratch (device globals; no allocation allowed) ----------------
__device__ int   g_cntI[NN];                       // in-degree (int)
__device__ int   g_off[NN + 1];                    // CSR offsets (by dst)
__device__ int   g_cur[NN];                        // fill cursors
__device__ int   g_csrc[NE];                       // CSR src lists
__device__ float g_cnt[NN];                        // in-degree (float)
__device__ float g_dinv[NN];                       // rsqrt(in-degree + 1) for GCN
__device__ __align__(16) float g_agg[NN * FI];     // gather accumulator (both SAGE layers)
__device__ __align__(16) float g_h1[NN * FH];      // SAGE1 output (post-relu)
__device__ __align__(16) float g_xw[NN * FC];      // h2 @ Wg

// ---------------- CSR build (edge_index is INT32 [2, E]) ----------------
__global__ void k_zero_cnt() {
    int i = blockIdx.x * blockDim.x + threadIdx.x;
    if (i < NN) g_cntI[i] = 0;
}

__global__ void k_count(const int* __restrict__ ei) {
    int e = blockIdx.x * blockDim.x + threadIdx.x;
    if (e < NE) atomicAdd(g_cntI + ei[NE + e], 1);
}

// single-block exclusive scan over NN counts -> offsets + cursors + cnt/dinv
__global__ void k_scan() {
    __shared__ int part[1024];
    const int CH = (NN + 1023) / 1024;   // 49
    int t = threadIdx.x;
    int base = t * CH;
    int sum = 0;
    for (int i = 0; i < CH; i++) {
        int idx = base + i;
        if (idx < NN) sum += g_cntI[idx];
    }
    part[t] = sum;
    __syncthreads();
    for (int off = 1; off < 1024; off <<= 1) {
        int v = (t >= off) ? part[t - off] : 0;
        __syncthreads();
        part[t] += v;
        __syncthreads();
    }
    int run = part[t] - sum;
    for (int i = 0; i < CH; i++) {
        int idx = base + i;
        if (idx < NN) {
            int c = g_cntI[idx];
            g_off[idx] = run;
            g_cur[idx] = run;
            run += c;
            g_cnt[idx] = (float)c;
            g_dinv[idx] = rsqrtf((float)c + 1.0f);
        }
    }
    if (t == 1023) g_off[NN] = NE;
}

__global__ void k_fill(const int* __restrict__ ei) {
    int e = blockIdx.x * blockDim.x + threadIdx.x;
    if (e >= NE) return;
    int src = ei[e];
    int dst = ei[NE + e];
    int pos = atomicAdd(g_cur + dst, 1);
    g_csrc[pos] = src;
}

// ---------------- gather aggregation (SPLIT kernels, high occupancy) ----------------
// warp per node; lane owns one float4; unroll x2 for MLP
__global__ void k_gather_x(const float* __restrict__ x) {
    int gt = blockIdx.x * blockDim.x + threadIdx.x;
    int node = gt >> 5;
    int lane = gt & 31;
    if (node >= NN) return;
    int beg = g_off[node], end = g_off[node + 1];
    float4 acc = make_float4(0.f, 0.f, 0.f, 0.f);
    int j = beg;
    for (; j + 1 < end; j += 2) {
        int s0 = g_csrc[j];
        int s1 = g_csrc[j + 1];
        float4 a = ((const float4*)(x + (size_t)s0 * FI))[lane];
        float4 b = ((const float4*)(x + (size_t)s1 * FI))[lane];
        acc.x += a.x + b.x; acc.y += a.y + b.y;
        acc.z += a.z + b.z; acc.w += a.w + b.w;
    }
    if (j < end) {
        int s0 = g_csrc[j];
        float4 a = ((const float4*)(x + (size_t)s0 * FI))[lane];
        acc.x += a.x; acc.y += a.y; acc.z += a.z; acc.w += a.w;
    }
    ((float4*)(g_agg + (size_t)node * FI))[lane] = acc;
}

__global__ void k_gather_h1() {
    int gt = blockIdx.x * blockDim.x + threadIdx.x;
    int node = gt >> 5;
    int lane = gt & 31;
    if (node >= NN) return;
    int beg = g_off[node], end = g_off[node + 1];
    float4 acc = make_float4(0.f, 0.f, 0.f, 0.f);
    int j = beg;
    for (; j + 1 < end; j += 2) {
        int s0 = g_csrc[j];
        int s1 = g_csrc[j + 1];
        float4 a = ((const float4*)(g_h1 + (size_t)s0 * FH))[lane];
        float4 b = ((const float4*)(g_h1 + (size_t)s1 * FH))[lane];
        acc.x += a.x + b.x; acc.y += a.y + b.y;
        acc.z += a.z + b.z; acc.w += a.w + b.w;
    }
    if (j < end) {
        int s0 = g_csrc[j];
        float4 a = ((const float4*)(g_h1 + (size_t)s0 * FH))[lane];
        acc.x += a.x; acc.y += a.y; acc.z += a.z; acc.w += a.w;
    }
    ((float4*)(g_agg + (size_t)node * FI))[lane] = acc;
}

// ---------------- SAGE layer 1 (round-11 version): persistent, weights staged once ----------------
// 16 nodes/tile, 2 per warp, lane owns 4 outputs
#define S1_NODES 16
__global__ void __launch_bounds__(256) k_sage1(const float* __restrict__ x,
                                               const float* __restrict__ W1l,
                                               const float* __restrict__ b1l,
                                               const float* __restrict__ W1r) {
    extern __shared__ float sm[];
    float* sWl = sm;                       // [128][128]
    float* sWr = sWl + FI * FH;            // [128][128]
    float* sM  = sWr + FI * FH;            // [16][128] mean
    float* sX  = sM + S1_NODES * FI;       // [16][128] x
    int t = threadIdx.x;

    for (int i = t; i < FI * FH / 4; i += 256) {
        ((float4*)sWl)[i] = ((const float4*)W1l)[i];
        ((float4*)sWr)[i] = ((const float4*)W1r)[i];
    }

    int warp = t >> 5, lane = t & 31;
    int ln0 = warp * 2, ln1 = warp * 2 + 1;
    float4 bb = ((const float4*)b1l)[lane];
    const float4* wl4 = (const float4*)sWl;
    const float4* wr4 = (const float4*)sWr;

    for (int tile = blockIdx.x; tile < NN / S1_NODES; tile += gridDim.x) {
        int nbase = tile * S1_NODES;
        __syncthreads();   // protect sM/sX reads from previous iteration
        for (int i = t; i < S1_NODES * FI / 4; i += 256) {
            int node = i >> 5;       // / (FI/4)
            int kk = i & 31;
            int gn = nbase + node;
            float scale = 1.0f / fmaxf(g_cnt[gn], 1.0f);
            float4 a = ((const float4*)(g_agg + (size_t)gn * FI))[kk];
            a.x *= scale; a.y *= scale; a.z *= scale; a.w *= scale;
            ((float4*)(sM + node * FI))[kk] = a;
            ((float4*)(sX + node * FI))[kk] = ((const float4*)(x + (size_t)gn * FI))[kk];
        }
        __syncthreads();

        float4 acc0 = bb, acc1 = bb;
        #pragma unroll 8
        for (int k = 0; k < FI; k++) {
            float4 wl = wl4[k * 32 + lane];
            float4 wr = wr4[k * 32 + lane];
            float m0 = sM[ln0 * FI + k], x0 = sX[ln0 * FI + k];
            float m1 = sM[ln1 * FI + k], x1 = sX[ln1 * FI + k];
            acc0.x += m0 * wl.x + x0 * wr.x;
            acc0.y += m0 * wl.y + x0 * wr.y;
            acc0.z += m0 * wl.z + x0 * wr.z;
            acc0.w += m0 * wl.w + x0 * wr.w;
            acc1.x += m1 * wl.x + x1 * wr.x;
            acc1.y += m1 * wl.y + x1 * wr.y;
            acc1.z += m1 * wl.z + x1 * wr.z;
            acc1.w += m1 * wl.w + x1 * wr.w;
        }
        int g0 = nbase + ln0, g1 = nbase + ln1;
        float4 r0 = make_float4(fmaxf(acc0.x, 0.f), fmaxf(acc0.y, 0.f), fmaxf(acc0.z, 0.f), fmaxf(acc0.w, 0.f));
        float4 r1 = make_float4(fmaxf(acc1.x, 0.f), fmaxf(acc1.y, 0.f), fmaxf(acc1.z, 0.f), fmaxf(acc1.w, 0.f));
        ((float4*)(g_h1 + (size_t)g0 * FH))[lane] = r0;
        ((float4*)(g_h1 + (size_t)g1 * FH))[lane] = r1;
    }
}

// ---------------- fused tail: SAGE2 GEMM + softmax + GCN GEMM + epilogue ----------------
// persistent; reads g_agg (pre-gathered) + g_h1. 32 nodes/tile; warp owns 4 nodes;
// lane owns cols (lane, lane+32). smem = 120KB.
#define T_NODES 32
__global__ void __launch_bounds__(256) k_tail(const float* __restrict__ W2l,
                                              const float* __restrict__ b2l,
                                              const float* __restrict__ W2r,
                                              const float* __restrict__ Wg,
                                              const float* __restrict__ bg,
                                              float* __restrict__ out) {
    extern __shared__ float sm[];
    float* sWl = sm;                       // [128][64]
    float* sWr = sWl + FH * FC;            // [128][64]
    float* sWg = sWr + FH * FC;            // [64][64]
    float* sM  = sWg + FC * FC;            // [32][128]
    float* sH  = sM + T_NODES * FH;        // [32][128]
    float* sH2 = sH + T_NODES * FH;        // [32][64]
    int t = threadIdx.x;
    int warp = t >> 5, lane = t & 31;
    int nl0 = warp * 4;
    int cA = lane, cB = lane + 32;

    for (int i = t; i < FH * FC / 4; i += 256) {
        ((float4*)sWl)[i] = ((const float4*)W2l)[i];
        ((float4*)sWr)[i] = ((const float4*)W2r)[i];
    }
    for (int i = t; i < FC * FC / 4; i += 256) ((float4*)sWg)[i] = ((const float4*)Wg)[i];
    float bA = b2l[cA], bB = b2l[cB];
    float bgA = bg[cA], bgB = bg[cB];

    const int ntiles = (NN + T_NODES - 1) / T_NODES;   // 1563
    for (int tile = blockIdx.x; tile < ntiles; tile += gridDim.x) {
        int nbase = tile * T_NODES;
        __syncthreads();

        // stage mean + h1 rows (coalesced, float4)
        for (int i = t; i < T_NODES * FH / 4; i += 256) {
            int node = i >> 5;       // / (FH/4)
            int kk = i & 31;
            int gn = nbase + node;
            if (gn < NN) {
                float scale = 1.0f / fmaxf(g_cnt[gn], 1.0f);
                float4 a = ((const float4*)(g_agg + (size_t)gn * FH))[kk];
                a.x *= scale; a.y *= scale; a.z *= scale; a.w *= scale;
                ((float4*)(sM + node * FH))[kk] = a;
                ((float4*)(sH + node * FH))[kk] = ((const float4*)(g_h1 + (size_t)gn * FH))[kk];
            } else {
                float4 z = make_float4(0.f, 0.f, 0.f, 0.f);
                ((float4*)(sM + node * FH))[kk] = z;
                ((float4*)(sH + node * FH))[kk] = z;
            }
        }
        __syncthreads();

        // SAGE2 GEMM: 4 nodes x 2 cols per lane
        float a00 = bA, a01 = bB, a10 = bA, a11 = bB;
        float a20 = bA, a21 = bB, a30 = bA, a31 = bB;
        #pragma unroll 4
        for (int k = 0; k < FH; k++) {
            float wlA = sWl[k * FC + cA], wlB = sWl[k * FC + cB];
            float wrA = sWr[k * FC + cA], wrB = sWr[k * FC + cB];
            float m0 = sM[(nl0 + 0) * FH + k], h0 = sH[(nl0 + 0) * FH + k];
            float m1 = sM[(nl0 + 1) * FH + k], h1 = sH[(nl0 + 1) * FH + k];
            float m2 = sM[(nl0 + 2) * FH + k], h2 = sH[(nl0 + 2) * FH + k];
            float m3 = sM[(nl0 + 3) * FH + k], h3 = sH[(nl0 + 3) * FH + k];
            a00 += m0 * wlA + h0 * wrA;  a01 += m0 * wlB + h0 * wrB;
            a10 += m1 * wlA + h1 * wrA;  a11 += m1 * wlB + h1 * wrB;
            a20 += m2 * wlA + h2 * wrA;  a21 += m2 * wlB + h2 * wrB;
            a30 += m3 * wlA + h3 * wrA;  a31 += m3 * wlB + h3 * wrB;
        }

        // softmax per node (row of 64 across warp: cols lane, lane+32)
        float eo0[4], eo1[4];
        {
            float v0[4] = {a00, a10, a20, a30};
            float v1[4] = {a01, a11, a21, a31};
            #pragma unroll
            for (int r = 0; r < 4; r++) {
                float mx = fmaxf(v0[r], v1[r]);
                #pragma unroll
                for (int o = 16; o > 0; o >>= 1) mx = fmaxf(mx, __shfl_xor_sync(0xFFFFFFFFu, mx, o));
                float e0 = __expf(v0[r] - mx), e1 = __expf(v1[r] - mx);
                float s = e0 + e1;
                #pragma unroll
                for (int o = 16; o > 0; o >>= 1) s += __shfl_xor_sync(0xFFFFFFFFu, s, o);
                float inv = 1.0f / s;
                eo0[r] = e0 * inv; eo1[r] = e1 * inv;
            }
        }
        // stage h2 rows (own warp's rows only -> syncwarp)
        #pragma unroll
        for (int r = 0; r < 4; r++) {
            sH2[(nl0 + r) * FC + cA] = eo0[r];
            sH2[(nl0 + r) * FC + cB] = eo1[r];
        }
        __syncwarp();

        // GCN GEMM: xw = h2 @ Wg
        float g00 = 0.f, g01 = 0.f, g10 = 0.f, g11 = 0.f;
        float g20 = 0.f, g21 = 0.f, g30 = 0.f, g31 = 0.f;
        #pragma unroll 4
        for (int k = 0; k < FC; k++) {
            float wA = sWg[k * FC + cA], wB = sWg[k * FC + cB];
            float f0 = sH2[(nl0 + 0) * FC + k];
            float f1 = sH2[(nl0 + 1) * FC + k];
            float f2 = sH2[(nl0 + 2) * FC + k];
            float f3 = sH2[(nl0 + 3) * FC + k];
            g00 += f0 * wA; g01 += f0 * wB;
            g10 += f1 * wA; g11 += f1 * wB;
            g20 += f2 * wA; g21 += f2 * wB;
            g30 += f3 * wA; g31 += f3 * wB;
        }

        // epilogue: g_xw + self-loop part of out
        float gx0[4] = {g00, g10, g20, g30};
        float gx1[4] = {g01, g11, g21, g31};
        #pragma unroll
        for (int r = 0; r < 4; r++) {
            int gn = nbase + nl0 + r;
            if (gn < NN) {
                float d = g_dinv[gn];
                float d2 = d * d;
                size_t base = (size_t)gn * FC;
                g_xw[base + cA] = gx0[r];
                g_xw[base + cB] = gx1[r];
                out[base + cA] = bgA + d2 * gx0[r];
                out[base + cB] = bgB + d2 * gx1[r];
            }
        }
    }
}

// ---------------- GCN edge gather: out[n] += dinv[n] * sum dinv[src]*xw[src] ----------------
__global__ void k_ggather(float* __restrict__ out) {
    int gt = blockIdx.x * blockDim.x + threadIdx.x;
    int node = gt >> 5;
    int lane = gt & 31;
    if (node >= NN) return;
    int beg = g_off[node], end = g_off[node + 1];
    float accA = 0.f, accB = 0.f;
    int j = beg;
    for (; j + 1 < end; j += 2) {
        int s0 = g_csrc[j], s1 = g_csrc[j + 1];
        float d0 = g_dinv[s0], d1 = g_dinv[s1];
        const float* r0 = g_xw + (size_t)s0 * FC;
        const float* r1 = g_xw + (size_t)s1 * FC;
        accA += d0 * r0[lane] + d1 * r1[lane];
        accB += d0 * r0[lane + 32] + d1 * r1[lane + 32];
    }
    if (j < end) {
        int s = g_csrc[j];
        float ds = g_dinv[s];
        const float* r = g_xw + (size_t)s * FC;
        accA += ds * r[lane];
        accB += ds * r[lane + 32];
    }
    float dn = g_dinv[node];
    float* row = out + (size_t)node * FC;
    row[lane] += dn * accA;
    row[lane + 32] += dn * accB;
}

// ---------------- launch ----------------
static void hx_check(const char* name, bool docheck, bool* bad) {
    if (!docheck || *bad) return;
    cudaError_t e = cudaStreamSynchronize(0);
    if (e != cudaSuccess) {
        fprintf(stderr, "HXDBG fault after %s: %s\n", name, cudaGetErrorString(e));
        fflush(stderr);
        *bad = true;
    }
}

extern "C" void kernel_launch(void* const* d_in, const int* in_sizes, int n_in,
                              void* d_out, int out_size) {
    const float* x   = (const float*)d_in[0];
    const int* ei    = (const int*)d_in[1];   // INT32 [2, E]
    const float* W1l = (const float*)d_in[2];
    const float* b1l = (const float*)d_in[3];
    const float* W1r = (const float*)d_in[4];
    const float* W2l = (const float*)d_in[5];
    const float* b2l = (const float*)d_in[6];
    const float* W2r = (const float*)d_in[7];
    const float* Wg  = (const float*)d_in[8];
    const float* bg  = (const float*)d_in[9];
    float* out = (float*)d_out;

    const int SMEM1 = (FI * FH * 2 + S1_NODES * FI * 2) * 4;                          // 147456
    const int SMEMT = (FH * FC * 2 + FC * FC + T_NODES * FH * 2 + T_NODES * FC) * 4;  // 122880
    cudaFuncSetAttribute(k_sage1, cudaFuncAttributeMaxDynamicSharedMemorySize, SMEM1);
    cudaFuncSetAttribute(k_tail, cudaFuncAttributeMaxDynamicSharedMemorySize, SMEMT);

    cudaStreamCaptureStatus st = cudaStreamCaptureStatusNone;
    cudaStreamIsCapturing(0, &st);
    bool docheck = (st == cudaStreamCaptureStatusNone);
    bool bad = false;

    // CSR build (by dst)
    k_zero_cnt<<<(NN + 255) / 256, 256>>>();
    hx_check("k_zero_cnt", docheck, &bad);
    k_count<<<(NE + 255) / 256, 256>>>(ei);
    hx_check("k_count", docheck, &bad);
    k_scan<<<1, 1024>>>();
    hx_check("k_scan", docheck, &bad);
    k_fill<<<(NE + 255) / 256, 256>>>(ei);
    hx_check("k_fill", docheck, &bad);

    // SAGE layer 1
    k_gather_x<<<(NN * 32 + 255) / 256, 256>>>(x);
    hx_check("k_gather_x", docheck, &bad);
    k_sage1<<<148, 256, SMEM1>>>(x, W1l, b1l, W1r);
    hx_check("k_sage1", docheck, &bad);

    // SAGE layer 2 + softmax + GCN (fused tail)
    k_gather_h1<<<(NN * 32 + 255) / 256, 256>>>();
    hx_check("k_gather_h1", docheck, &bad);
    k_tail<<<148, 256, SMEMT>>>(W2l, b2l, W2r, Wg, bg, out);
    hx_check("k_tail", docheck, &bad);
    k_ggather<<<(NN * 32 + 255) / 256, 256>>>(out);
    hx_check("k_ggather", docheck, &bad);
}

// round 15
// speedup vs baseline: 1.2054x; 1.0373x over previous
#include <cuda_runtime.h>
#include <cstdio>

#define NN 50000
#define NE 800000
#define FI 128
#define FH 128
#define FC 64

// ---------------- scratch (device globals; no allocation allowed) ----------------
__device__ int   g_cntI[NN];                       // in-degree (int)
__device__ int   g_off[NN + 1];                    // CSR offsets (by dst)
__device__ int   g_cur[NN];                        // fill cursors
__device__ int   g_csrc[NE];                       // CSR src lists
__device__ float g_cnt[NN];                        // in-degree (float)
__device__ float g_dinv[NN];                       // rsqrt(in-degree + 1) for GCN
__device__ __align__(16) float g_agg[NN * FI];     // layer-1 gather accumulator (128-wide)
__device__ __align__(16) float g_h1[NN * FH];      // SAGE1 output (post-relu)
__device__ __align__(16) float g_z[NN * FC];       // Z = h1 @ W2l  (gather-after-projection)
__device__ __align__(16) float g_aggz[NN * FC];    // gathered Z (64-wide)
__device__ __align__(16) float g_h2[NN * FC];      // SAGE2 output (post-softmax)
__device__ __align__(16) float g_xw[NN * FC];      // h2 @ Wg

// ---------------- CSR build (edge_index is INT32 [2, E]) ----------------
__global__ void k_zero_cnt() {
    int i = blockIdx.x * blockDim.x + threadIdx.x;
    if (i < NN) g_cntI[i] = 0;
}

__global__ void k_count(const int* __restrict__ ei) {
    int e = blockIdx.x * blockDim.x + threadIdx.x;
    if (e < NE) atomicAdd(g_cntI + ei[NE + e], 1);
}

// single-block exclusive scan over NN counts -> offsets + cursors + cnt/dinv
__global__ void k_scan() {
    __shared__ int part[1024];
    const int CH = (NN + 1023) / 1024;   // 49
    int t = threadIdx.x;
    int base = t * CH;
    int sum = 0;
    for (int i = 0; i < CH; i++) {
        int idx = base + i;
        if (idx < NN) sum += g_cntI[idx];
    }
    part[t] = sum;
    __syncthreads();
    for (int off = 1; off < 1024; off <<= 1) {
        int v = (t >= off) ? part[t - off] : 0;
        __syncthreads();
        part[t] += v;
        __syncthreads();
    }
    int run = part[t] - sum;
    for (int i = 0; i < CH; i++) {
        int idx = base + i;
        if (idx < NN) {
            int c = g_cntI[idx];
            g_off[idx] = run;
            g_cur[idx] = run;
            run += c;
            g_cnt[idx] = (float)c;
            g_dinv[idx] = rsqrtf((float)c + 1.0f);
        }
    }
    if (t == 1023) g_off[NN] = NE;
}

__global__ void k_fill(const int* __restrict__ ei) {
    int e = blockIdx.x * blockDim.x + threadIdx.x;
    if (e >= NE) return;
    int src = ei[e];
    int dst = ei[NE + e];
    int pos = atomicAdd(g_cur + dst, 1);
    g_csrc[pos] = src;
}

// ---------------- 128-wide gather: agg[n] = sum_{in(n)} x[src] ----------------
// warp per node; lane owns one float4; unroll x2 for MLP
__global__ void k_gather_x(const float* __restrict__ x) {
    int gt = blockIdx.x * blockDim.x + threadIdx.x;
    int node = gt >> 5;
    int lane = gt & 31;
    if (node >= NN) return;
    int beg = g_off[node], end = g_off[node + 1];
    float4 acc = make_float4(0.f, 0.f, 0.f, 0.f);
    int j = beg;
    for (; j + 1 < end; j += 2) {
        int s0 = g_csrc[j];
        int s1 = g_csrc[j + 1];
        float4 a = ((const float4*)(x + (size_t)s0 * FI))[lane];
        float4 b = ((const float4*)(x + (size_t)s1 * FI))[lane];
        acc.x += a.x + b.x; acc.y += a.y + b.y;
        acc.z += a.z + b.z; acc.w += a.w + b.w;
    }
    if (j < end) {
        int s0 = g_csrc[j];
        float4 a = ((const float4*)(x + (size_t)s0 * FI))[lane];
        acc.x += a.x; acc.y += a.y; acc.z += a.z; acc.w += a.w;
    }
    ((float4*)(g_agg + (size_t)node * FI))[lane] = acc;
}

// ---------------- 64-wide gather: aggz[n] = sum_{in(n)} Z[src] ----------------
// warp per node; lane owns one float2 (64 floats); unroll x2
__global__ void k_gather_z() {
    int gt = blockIdx.x * blockDim.x + threadIdx.x;
    int node = gt >> 5;
    int lane = gt & 31;
    if (node >= NN) return;
    int beg = g_off[node], end = g_off[node + 1];
    float2 acc = make_float2(0.f, 0.f);
    int j = beg;
    for (; j + 1 < end; j += 2) {
        int s0 = g_csrc[j];
        int s1 = g_csrc[j + 1];
        float2 a = ((const float2*)(g_z + (size_t)s0 * FC))[lane];
        float2 b = ((const float2*)(g_z + (size_t)s1 * FC))[lane];
        acc.x += a.x + b.x; acc.y += a.y + b.y;
    }
    if (j < end) {
        int s0 = g_csrc[j];
        float2 a = ((const float2*)(g_z + (size_t)s0 * FC))[lane];
        acc.x += a.x; acc.y += a.y;
    }
    ((float2*)(g_aggz + (size_t)node * FC))[lane] = acc;
}

// ---------------- SAGE layer 1: persistent, weights staged once (R11 version) ----------------
// 16 nodes/tile, 2 per warp, lane owns 4 outputs
#define S1_NODES 16
__global__ void __launch_bounds__(256) k_sage1(const float* __restrict__ x,
                                               const float* __restrict__ W1l,
                                               const float* __restrict__ b1l,
                                               const float* __restrict__ W1r) {
    extern __shared__ float sm[];
    float* sWl = sm;                       // [128][128]
    float* sWr = sWl + FI * FH;            // [128][128]
    float* sM  = sWr + FI * FH;            // [16][128] mean
    float* sX  = sM + S1_NODES * FI;       // [16][128] x
    int t = threadIdx.x;

    for (int i = t; i < FI * FH / 4; i += 256) {
        ((float4*)sWl)[i] = ((const float4*)W1l)[i];
        ((float4*)sWr)[i] = ((const float4*)W1r)[i];
    }

    int warp = t >> 5, lane = t & 31;
    int ln0 = warp * 2, ln1 = warp * 2 + 1;
    float4 bb = ((const float4*)b1l)[lane];
    const float4* wl4 = (const float4*)sWl;
    const float4* wr4 = (const float4*)sWr;

    for (int tile = blockIdx.x; tile < NN / S1_NODES; tile += gridDim.x) {
        int nbase = tile * S1_NODES;
        __syncthreads();
        for (int i = t; i < S1_NODES * FI / 4; i += 256) {
            int node = i >> 5;
            int kk = i & 31;
            int gn = nbase + node;
            float scale = 1.0f / fmaxf(g_cnt[gn], 1.0f);
            float4 a = ((const float4*)(g_agg + (size_t)gn * FI))[kk];
            a.x *= scale; a.y *= scale; a.z *= scale; a.w *= scale;
            ((float4*)(sM + node * FI))[kk] = a;
            ((float4*)(sX + node * FI))[kk] = ((const float4*)(x + (size_t)gn * FI))[kk];
        }
        __syncthreads();

        float4 acc0 = bb, acc1 = bb;
        #pragma unroll 8
        for (int k = 0; k < FI; k++) {
            float4 wl = wl4[k * 32 + lane];
            float4 wr = wr4[k * 32 + lane];
            float m0 = sM[ln0 * FI + k], x0 = sX[ln0 * FI + k];
            float m1 = sM[ln1 * FI + k], x1 = sX[ln1 * FI + k];
            acc0.x += m0 * wl.x + x0 * wr.x;
            acc0.y += m0 * wl.y + x0 * wr.y;
            acc0.z += m0 * wl.z + x0 * wr.z;
            acc0.w += m0 * wl.w + x0 * wr.w;
            acc1.x += m1 * wl.x + x1 * wr.x;
            acc1.y += m1 * wl.y + x1 * wr.y;
            acc1.z += m1 * wl.z + x1 * wr.z;
            acc1.w += m1 * wl.w + x1 * wr.w;
        }
        int g0 = nbase + ln0, g1 = nbase + ln1;
        float4 r0 = make_float4(fmaxf(acc0.x, 0.f), fmaxf(acc0.y, 0.f), fmaxf(acc0.z, 0.f), fmaxf(acc0.w, 0.f));
        float4 r1 = make_float4(fmaxf(acc1.x, 0.f), fmaxf(acc1.y, 0.f), fmaxf(acc1.z, 0.f), fmaxf(acc1.w, 0.f));
        ((float4*)(g_h1 + (size_t)g0 * FH))[lane] = r0;
        ((float4*)(g_h1 + (size_t)g1 * FH))[lane] = r1;
    }
}

// ---------------- Z = h1 @ W2l (projection BEFORE gather; high-occupancy) ----------------
// 16 nodes/block; warp owns 2 nodes; lane owns cols (lane, lane+32); 40KB static smem
#define P_NODES 16
__global__ void __launch_bounds__(256) k_proj(const float* __restrict__ W2l) {
    __shared__ float sW[FH * FC];          // [128][64] 32KB
    __shared__ float sH[P_NODES * FH];     // [16][128]  8KB
    int t = threadIdx.x;
    for (int i = t; i < FH * FC / 4; i += 256)
        ((float4*)sW)[i] = ((const float4*)W2l)[i];

    int nbase = blockIdx.x * P_NODES;
    for (int i = t; i < P_NODES * FH / 4; i += 256) {
        int node = i >> 5;
        int kk = i & 31;
        int gn = nbase + node;
        ((float4*)(sH + node * FH))[kk] = ((const float4*)(g_h1 + (size_t)gn * FH))[kk];
    }
    __syncthreads();

    int warp = t >> 5, lane = t & 31;
    int ln0 = warp * 2, ln1 = warp * 2 + 1;
    int cA = lane, cB = lane + 32;
    float a00 = 0.f, a01 = 0.f, a10 = 0.f, a11 = 0.f;
    #pragma unroll 8
    for (int k = 0; k < FH; k++) {
        float wA = sW[k * FC + cA], wB = sW[k * FC + cB];
        float h0 = sH[ln0 * FH + k];
        float h1 = sH[ln1 * FH + k];
        a00 += h0 * wA; a01 += h0 * wB;
        a10 += h1 * wA; a11 += h1 * wB;
    }
    int g0 = nbase + ln0, g1 = nbase + ln1;
    g_z[(size_t)g0 * FC + cA] = a00;
    g_z[(size_t)g0 * FC + cB] = a01;
    g_z[(size_t)g1 * FC + cA] = a10;
    g_z[(size_t)g1 * FC + cB] = a11;
}

// ---------------- SAGE2 + softmax: h2 = softmax(aggz/cnt + h1 @ W2r + b2l) ----------------
// 16 nodes/block; warp owns 2 nodes; lane owns cols (lane, lane+32); 40KB static smem
__global__ void __launch_bounds__(256) k_sage2b(const float* __restrict__ b2l,
                                                const float* __restrict__ W2r) {
    __shared__ float sW[FH * FC];          // [128][64] 32KB
    __shared__ float sH[P_NODES * FH];     // [16][128]  8KB
    int t = threadIdx.x;
    for (int i = t; i < FH * FC / 4; i += 256)
        ((float4*)sW)[i] = ((const float4*)W2r)[i];

    int nbase = blockIdx.x * P_NODES;
    for (int i = t; i < P_NODES * FH / 4; i += 256) {
        int node = i >> 5;
        int kk = i & 31;
        int gn = nbase + node;
        ((float4*)(sH + node * FH))[kk] = ((const float4*)(g_h1 + (size_t)gn * FH))[kk];
    }
    __syncthreads();

    int warp = t >> 5, lane = t & 31;
    int ln0 = warp * 2, ln1 = warp * 2 + 1;
    int cA = lane, cB = lane + 32;
    float bA = b2l[cA], bB = b2l[cB];
    float a00 = bA, a01 = bB, a10 = bA, a11 = bB;
    #pragma unroll 8
    for (int k = 0; k < FH; k++) {
        float wA = sW[k * FC + cA], wB = sW[k * FC + cB];
        float h0 = sH[ln0 * FH + k];
        float h1 = sH[ln1 * FH + k];
        a00 += h0 * wA; a01 += h0 * wB;
        a10 += h1 * wA; a11 += h1 * wB;
    }
    int g0 = nbase + ln0, g1 = nbase + ln1;
    // add mean of gathered Z
    float s0 = 1.0f / fmaxf(g_cnt[g0], 1.0f);
    float s1 = 1.0f / fmaxf(g_cnt[g1], 1.0f);
    a00 += s0 * g_aggz[(size_t)g0 * FC + cA];
    a01 += s0 * g_aggz[(size_t)g0 * FC + cB];
    a10 += s1 * g_aggz[(size_t)g1 * FC + cA];
    a11 += s1 * g_aggz[(size_t)g1 * FC + cB];

    // inline softmax per node (row of 64 across warp: cols lane, lane+32)
    {
        float mx = fmaxf(a00, a01);
        #pragma unroll
        for (int o = 16; o > 0; o >>= 1) mx = fmaxf(mx, __shfl_xor_sync(0xFFFFFFFFu, mx, o));
        float e0 = __expf(a00 - mx), e1 = __expf(a01 - mx);
        float s = e0 + e1;
        #pragma unroll
        for (int o = 16; o > 0; o >>= 1) s += __shfl_xor_sync(0xFFFFFFFFu, s, o);
        float inv = 1.0f / s;
        g_h2[(size_t)g0 * FC + cA] = e0 * inv;
        g_h2[(size_t)g0 * FC + cB] = e1 * inv;
    }
    {
        float mx = fmaxf(a10, a11);
        #pragma unroll
        for (int o = 16; o > 0; o >>= 1) mx = fmaxf(mx, __shfl_xor_sync(0xFFFFFFFFu, mx, o));
        float e0 = __expf(a10 - mx), e1 = __expf(a11 - mx);
        float s = e0 + e1;
        #pragma unroll
        for (int o = 16; o > 0; o >>= 1) s += __shfl_xor_sync(0xFFFFFFFFu, s, o);
        float inv = 1.0f / s;
        g_h2[(size_t)g1 * FC + cA] = e0 * inv;
        g_h2[(size_t)g1 * FC + cB] = e1 * inv;
    }
}

// ---------------- GCN gemm + self-loop/bias epilogue (R11 version) ----------------
#define G_NODES 16
__global__ void __launch_bounds__(256) k_gcn(const float* __restrict__ Wg,
                                             const float* __restrict__ bg,
                                             float* __restrict__ out) {
    __shared__ float sW[FC * FC];          // 16KB
    __shared__ float sF[G_NODES * FC];     // 4KB
    int t = threadIdx.x;
    for (int i = t; i < FC * FC / 4; i += 256)
        ((float4*)sW)[i] = ((const float4*)Wg)[i];

    int nbase = blockIdx.x * G_NODES;
    for (int i = t; i < G_NODES * FC / 4; i += 256) {
        int node = i >> 4;
        int kk = i & 15;
        int gn = nbase + node;
        ((float4*)(sF + node * FC))[kk] = ((const float4*)(g_h2 + (size_t)gn * FC))[kk];
    }
    __syncthreads();

    int warp = t >> 5, lane = t & 31;
    int ln0 = warp * 2, ln1 = warp * 2 + 1;
    int cA = lane, cB = lane + 32;
    float a00 = 0.f, a01 = 0.f, a10 = 0.f, a11 = 0.f;
    #pragma unroll 8
    for (int k = 0; k < FC; k++) {
        float wA = sW[k * FC + cA], wB = sW[k * FC + cB];
        float f0 = sF[ln0 * FC + k];
        float f1 = sF[ln1 * FC + k];
        a00 += f0 * wA; a01 += f0 * wB;
        a10 += f1 * wA; a11 += f1 * wB;
    }
    int g0 = nbase + ln0, g1 = nbase + ln1;
    g_xw[(size_t)g0 * FC + cA] = a00;
    g_xw[(size_t)g0 * FC + cB] = a01;
    g_xw[(size_t)g1 * FC + cA] = a10;
    g_xw[(size_t)g1 * FC + cB] = a11;
    float bA = bg[cA], bB = bg[cB];
    float d0 = g_dinv[g0]; d0 *= d0;
    float d1 = g_dinv[g1]; d1 *= d1;
    out[(size_t)g0 * FC + cA] = bA + d0 * a00;
    out[(size_t)g0 * FC + cB] = bB + d0 * a01;
    out[(size_t)g1 * FC + cA] = bA + d1 * a10;
    out[(size_t)g1 * FC + cB] = bB + d1 * a11;
}

// ---------------- GCN edge gather: out[n] += dinv[n] * sum dinv[src]*xw[src] ----------------
__global__ void k_ggather(float* __restrict__ out) {
    int gt = blockIdx.x * blockDim.x + threadIdx.x;
    int node = gt >> 5;
    int lane = gt & 31;
    if (node >= NN) return;
    int beg = g_off[node], end = g_off[node + 1];
    float accA = 0.f, accB = 0.f;
    int j = beg;
    for (; j + 1 < end; j += 2) {
        int s0 = g_csrc[j], s1 = g_csrc[j + 1];
        float d0 = g_dinv[s0], d1 = g_dinv[s1];
        const float* r0 = g_xw + (size_t)s0 * FC;
        const float* r1 = g_xw + (size_t)s1 * FC;
        accA += d0 * r0[lane] + d1 * r1[lane];
        accB += d0 * r0[lane + 32] + d1 * r1[lane + 32];
    }
    if (j < end) {
        int s = g_csrc[j];
        float ds = g_dinv[s];
        const float* r = g_xw + (size_t)s * FC;
        accA += ds * r[lane];
        accB += ds * r[lane + 32];
    }
    float dn = g_dinv[node];
    float* row = out + (size_t)node * FC;
    row[lane] += dn * accA;
    row[lane + 32] += dn * accB;
}

// ---------------- launch ----------------
static void hx_check(const char* name, bool docheck, bool* bad) {
    if (!docheck || *bad) return;
    cudaError_t e = cudaStreamSynchronize(0);
    if (e != cudaSuccess) {
        fprintf(stderr, "HXDBG fault after %s: %s\n", name, cudaGetErrorString(e));
        fflush(stderr);
        *bad = true;
    }
}

extern "C" void kernel_launch(void* const* d_in, const int* in_sizes, int n_in,
                              void* d_out, int out_size) {
    const float* x   = (const float*)d_in[0];
    const int* ei    = (const int*)d_in[1];   // INT32 [2, E]
    const float* W1l = (const float*)d_in[2];
    const float* b1l = (const float*)d_in[3];
    const float* W1r = (const float*)d_in[4];
    const float* W2l = (const float*)d_in[5];
    const float* b2l = (const float*)d_in[6];
    const float* W2r = (const float*)d_in[7];
    const float* Wg  = (const float*)d_in[8];
    const float* bg  = (const float*)d_in[9];
    float* out = (float*)d_out;

    const int SMEM1 = (FI * FH * 2 + S1_NODES * FI * 2) * 4;   // 147456
    cudaFuncSetAttribute(k_sage1, cudaFuncAttributeMaxDynamicSharedMemorySize, SMEM1);

    cudaStreamCaptureStatus st = cudaStreamCaptureStatusNone;
    cudaStreamIsCapturing(0, &st);
    bool docheck = (st == cudaStreamCaptureStatusNone);
    bool bad = false;

    // CSR build (by dst)
    k_zero_cnt<<<(NN + 255) / 256, 256>>>();
    hx_check("k_zero_cnt", docheck, &bad);
    k_count<<<(NE + 255) / 256, 256>>>(ei);
    hx_check("k_count", docheck, &bad);
    k_scan<<<1, 1024>>>();
    hx_check("k_scan", docheck, &bad);
    k_fill<<<(NE + 255) / 256, 256>>>(ei);
    hx_check("k_fill", docheck, &bad);

    // SAGE layer 1
    k_gather_x<<<(NN * 32 + 255) / 256, 256>>>(x);
    hx_check("k_gather_x", docheck, &bad);
    k_sage1<<<148, 256, SMEM1>>>(x, W1l, b1l, W1r);
    hx_check("k_sage1", docheck, &bad);

    // SAGE layer 2: project -> gather (64-wide) -> combine + softmax
    k_proj<<<NN / P_NODES, 256>>>(W2l);
    hx_check("k_proj", docheck, &bad);
    k_gather_z<<<(NN * 32 + 255) / 256, 256>>>();
    hx_check("k_gather_z", docheck, &bad);
    k_sage2b<<<NN / P_NODES, 256>>>(b2l, W2r);
    hx_check("k_sage2b", docheck, &bad);

    // GCN
    k_gcn<<<NN / G_NODES, 256>>>(Wg, bg, out);
    hx_check("k_gcn", docheck, &bad);
    k_ggather<<<(NN * 32 + 255) / 256, 256>>>(out);
    hx_check("k_ggather", docheck, &bad);
}